// round 11
// baseline (speedup 1.0000x reference)
#include <cuda_runtime.h>
#include <cuda_bf16.h>
#include <math.h>
#include <float.h>

// Problem constants
#define BATCH   2
#define SEQ     2048
#define HID     2048
#define NHEADS  16
#define NKV     4
#define HDIM    256
#define QKDIM   (NHEADS*HDIM)   // 4096
#define KVDIM   (NKV*HDIM)      // 1024
#define MROWS   (BATCH*SEQ)     // 4096

// ---------------- scratch (flat layouts) ------------------------------------
__device__ float g_q[MROWS*QKDIM];                       // [m, h*256+d]
__device__ float g_k[MROWS*KVDIM];                       // [m, kv*256+d]
__device__ float g_v[MROWS*KVDIM];
__device__ float g_attn[MROWS*QKDIM];                    // [m, h*256+d]
__device__ float g_scores[(size_t)BATCH*NHEADS*SEQ*SEQ]; // [bh][q][k] 512MB

// ---------------- naive tiled GEMM: C[m*N+n] = A(MxK) @ B(KxN) -------------
__global__ void ngemm(const float* __restrict__ A, const float* __restrict__ B,
                      float* __restrict__ C, int M, int N, int K)
{
    __shared__ float As[16][16];
    __shared__ float Bs[16][17];
    const int tx = threadIdx.x, ty = threadIdx.y;
    const int m = blockIdx.y * 16 + ty;
    const int n = blockIdx.x * 16 + tx;
    float acc = 0.f;
    for (int k0 = 0; k0 < K; k0 += 16) {
        As[ty][tx] = A[(size_t)m * K + k0 + tx];
        Bs[ty][tx] = B[(size_t)(k0 + ty) * N + n];
        __syncthreads();
#pragma unroll
        for (int t = 0; t < 16; t++) acc += As[ty][t] * Bs[t][tx];
        __syncthreads();
    }
    C[(size_t)m * N + n] = acc;
}

// ---------------- RoPE, SIGN-FLIPPED rotation (rotate_half = (x2, -x1)) ----
// halves pairing (t, t+128), freq = 10000^(-t/128), pos from input.
// new_x1 = x1*cos + x2*sin ; new_x2 = x2*cos - x1*sin
__global__ void rope_flat(float* __restrict__ buf,
                          const int* __restrict__ pos_ids, int ncols)
{
    const int nh = ncols >> 8;
    const long total = (long)MROWS * nh * 128;
    for (long idx = (long)blockIdx.x * blockDim.x + threadIdx.x; idx < total;
         idx += (long)gridDim.x * blockDim.x) {
        const int  t = (int)(idx & 127);       // pair index 0..127
        const long r = idx >> 7;
        const int  h = (int)(r % nh);
        const int  m = (int)(r / nh);
        const int  b = m >> 11;
        const int  s = m & 2047;
        const float pos = (float)pos_ids[b * SEQ + s];
        const float invf = powf(10000.0f, -(float)t * (1.0f / 128.0f));
        float c, sn;
        sincosf(pos * invf, &c, &sn);
        float* p = buf + (size_t)m * ncols + h * 256;
        const float x1 = p[t];
        const float x2 = p[t + 128];
        p[t]       = x1 * c + x2 * sn;   // sign-flipped convention
        p[t + 128] = x2 * c - x1 * sn;
    }
}

// ---------------- scores: S[bh][q][k] = (Q[q]·K[k])/16 + mask --------------
__global__ void score_flat(const float* __restrict__ Qf,
                           const float* __restrict__ Kf,
                           const float* __restrict__ mask,
                           float* __restrict__ Sc)
{
    const int bh = blockIdx.z;
    const int b = bh >> 4, h = bh & 15, kvh = h >> 2; // repeat_kv: h -> h/4
    const int tx = threadIdx.x, ty = threadIdx.y;
    const int q = blockIdx.y * 16 + ty;
    const int k = blockIdx.x * 16 + tx;
    __shared__ float Qs[16][16];
    __shared__ float Ks[16][17];
    float acc = 0.f;
    for (int d0 = 0; d0 < HDIM; d0 += 16) {
        Qs[ty][tx] = Qf[(size_t)(b*SEQ + q) * QKDIM + h*256 + d0 + tx];
        Ks[ty][tx] = Kf[(size_t)(b*SEQ + blockIdx.x*16 + ty) * KVDIM + kvh*256 + d0 + tx];
        __syncthreads();
#pragma unroll
        for (int t = 0; t < 16; t++) acc += Qs[ty][t] * Ks[tx][t];
        __syncthreads();
    }
    const float mval = mask[((size_t)b * SEQ + q) * SEQ + k];
    Sc[(size_t)bh * SEQ * SEQ + (size_t)q * SEQ + k] = acc * 0.0625f + mval;
}

// ---------------- softmax: one block per row, in place ---------------------
__global__ void softmax_kernel(float* __restrict__ Sc)
{
    float* p = Sc + (size_t)blockIdx.x * SEQ;
    __shared__ float red[256];
    const int tid = threadIdx.x;
    float m = -3.0e38f;
    for (int i = tid; i < SEQ; i += 256) m = fmaxf(m, p[i]);
    red[tid] = m; __syncthreads();
    for (int s = 128; s > 0; s >>= 1) {
        if (tid < s) red[tid] = fmaxf(red[tid], red[tid + s]);
        __syncthreads();
    }
    m = red[0]; __syncthreads();
    float sum = 0.f;
    for (int i = tid; i < SEQ; i += 256) {
        const float e = expf(p[i] - m);
        p[i] = e;
        sum += e;
    }
    red[tid] = sum; __syncthreads();
    for (int s = 128; s > 0; s >>= 1) {
        if (tid < s) red[tid] += red[tid + s];
        __syncthreads();
    }
    const float inv = 1.f / red[0];
    for (int i = tid; i < SEQ; i += 256) p[i] *= inv;
}

// ---------------- PV: attn[m, h*256+d] = sum_k P[bh][q][k] V[.,kvh*256+d] --
__global__ void pv_flat(const float* __restrict__ Sc,
                        const float* __restrict__ Vf,
                        float* __restrict__ Out)
{
    const int bh = blockIdx.z;
    const int b = bh >> 4, h = bh & 15, kvh = h >> 2;
    const int tx = threadIdx.x, ty = threadIdx.y;
    const int q = blockIdx.y * 16 + ty;
    const int d = blockIdx.x * 16 + tx;
    const float* P = Sc + (size_t)bh * SEQ * SEQ;
    __shared__ float Ps[16][16];
    __shared__ float Vs[16][17];
    float acc = 0.f;
    for (int k0 = 0; k0 < SEQ; k0 += 16) {
        Ps[ty][tx] = P[(size_t)q * SEQ + k0 + tx];
        Vs[ty][tx] = Vf[(size_t)(b*SEQ + k0 + ty) * KVDIM + kvh*256 + d];
        __syncthreads();
#pragma unroll
        for (int t = 0; t < 16; t++) acc += Ps[ty][t] * Vs[t][tx];
        __syncthreads();
    }
    Out[(size_t)(b*SEQ + q) * QKDIM + h*256 + d] = acc;
}

// ---------------- launch ---------------------------------------------------
extern "C" void kernel_launch(void* const* d_in, const int* in_sizes, int n_in,
                              void* d_out, int out_size)
{
    const float* hidden = (const float*)d_in[0];
    const float* mask   = (const float*)d_in[1];
    const int*   pos    = (const int*)  d_in[2];
    const float* Wq     = (const float*)d_in[3];
    const float* Wk     = (const float*)d_in[4];
    const float* Wv     = (const float*)d_in[5];
    const float* Wo     = (const float*)d_in[6];
    float* out = (float*)d_out;

    float *qf, *kf, *vf, *af, *sb;
    cudaGetSymbolAddress((void**)&qf, g_q);
    cudaGetSymbolAddress((void**)&kf, g_k);
    cudaGetSymbolAddress((void**)&vf, g_v);
    cudaGetSymbolAddress((void**)&af, g_attn);
    cudaGetSymbolAddress((void**)&sb, g_scores);

    dim3 blk(16, 16);

    // projections — plain flat GEMMs
    ngemm<<<dim3(QKDIM/16, MROWS/16), blk>>>(hidden, Wq, qf, MROWS, QKDIM, HID);
    ngemm<<<dim3(KVDIM/16, MROWS/16), blk>>>(hidden, Wk, kf, MROWS, KVDIM, HID);
    ngemm<<<dim3(KVDIM/16, MROWS/16), blk>>>(hidden, Wv, vf, MROWS, KVDIM, HID);

    // RoPE in-place, sign-flipped convention, both batches
    rope_flat<<<2048, 256>>>(qf, pos, QKDIM);
    rope_flat<<<2048, 256>>>(kf, pos, KVDIM);

    // attention
    score_flat<<<dim3(SEQ/16, SEQ/16, BATCH*NHEADS), blk>>>(qf, kf, mask, sb);
    softmax_kernel<<<BATCH*NHEADS*SEQ, 256>>>(sb);
    pv_flat<<<dim3(HDIM/16, SEQ/16, BATCH*NHEADS), blk>>>(sb, vf, af);

    // output projection
    ngemm<<<dim3(HID/16, MROWS/16), blk>>>(af, Wo, out, MROWS, HID, QKDIM);
}

// round 12
// speedup vs baseline: 5.2845x; 5.2845x over previous
#include <cuda_runtime.h>
#include <cuda_bf16.h>
#include <math.h>
#include <float.h>

// Problem constants
#define BATCH   2
#define SEQ     2048
#define HID     2048
#define NHEADS  16
#define NKV     4
#define HDIM    256
#define QKDIM   (NHEADS*HDIM)   // 4096
#define KVDIM   (NKV*HDIM)      // 1024

// ---------------- scratch (device globals) ---------------------------------
__device__ float g_q[BATCH*NHEADS*SEQ*HDIM];   // [b,h,s,d]
__device__ float g_k[BATCH*NKV*SEQ*HDIM];      // [b,kv,s,d]
__device__ float g_v[BATCH*NKV*SEQ*HDIM];
__device__ float g_attn[BATCH*SEQ*QKDIM];      // [b,s,h*d]

// ---------------- SGEMM: C = A(MxK) * B(KxN), fp32, 128x128x16 -------------
#define BM 128
#define BN 128
#define BKT 16
#define TM 8
#define TN 8

// mode 0: plain C[m*N+n]
// mode 1: Q layout  [(b*16+h)*2048+s]*256+d
// mode 2: KV layout [(b*4 +h)*2048+s]*256+d
__global__ __launch_bounds__(256) void sgemm_kernel(
    const float* __restrict__ A, const float* __restrict__ B,
    float* __restrict__ C, int M, int N, int K, int mode)
{
    __shared__ float As[BKT][BM + 4];
    __shared__ float Bs[BKT][BN];

    const int tid = threadIdx.x;
    const int tx = tid & 15;
    const int ty = tid >> 4;
    const int bm = blockIdx.y * BM;
    const int bn = blockIdx.x * BN;

    float acc[TM][TN];
#pragma unroll
    for (int i = 0; i < TM; i++)
#pragma unroll
        for (int j = 0; j < TN; j++) acc[i][j] = 0.f;

    const int arow = tid >> 2;        // 0..63
    const int acol = (tid & 3) * 4;   // 0,4,8,12
    const int brow = tid >> 5;        // 0..7
    const int bcol = (tid & 31) * 4;

    for (int k0 = 0; k0 < K; k0 += BKT) {
#pragma unroll
        for (int r = 0; r < 2; r++) {
            float4 v = *(const float4*)&A[(size_t)(bm + arow + r*64) * K + k0 + acol];
            As[acol + 0][arow + r*64] = v.x;
            As[acol + 1][arow + r*64] = v.y;
            As[acol + 2][arow + r*64] = v.z;
            As[acol + 3][arow + r*64] = v.w;
        }
#pragma unroll
        for (int r = 0; r < 2; r++) {
            *(float4*)&Bs[brow + r*8][bcol] =
                *(const float4*)&B[(size_t)(k0 + brow + r*8) * N + bn + bcol];
        }
        __syncthreads();

#pragma unroll
        for (int kk = 0; kk < BKT; kk++) {
            float a[TM], b[TN];
            *(float4*)&a[0] = *(const float4*)&As[kk][ty*8];
            *(float4*)&a[4] = *(const float4*)&As[kk][ty*8 + 4];
            *(float4*)&b[0] = *(const float4*)&Bs[kk][tx*8];
            *(float4*)&b[4] = *(const float4*)&Bs[kk][tx*8 + 4];
#pragma unroll
            for (int i = 0; i < TM; i++)
#pragma unroll
                for (int j = 0; j < TN; j++)
                    acc[i][j] += a[i] * b[j];
        }
        __syncthreads();
    }

#pragma unroll
    for (int i = 0; i < TM; i++) {
        const int m = bm + ty*8 + i;
#pragma unroll
        for (int j = 0; j < TN; j++) {
            const int n = bn + tx*8 + j;
            const float val = acc[i][j];
            if (mode == 0) {
                C[(size_t)m * N + n] = val;
            } else if (mode == 1) {
                const int bb = m >> 11, s = m & 2047;
                const int h = n >> 8,  d = n & 255;
                C[(((size_t)(bb*NHEADS + h))*SEQ + s)*HDIM + d] = val;
            } else {
                const int bb = m >> 11, s = m & 2047;
                const int h = n >> 8,  d = n & 255;
                C[(((size_t)(bb*NKV + h))*SEQ + s)*HDIM + d] = val;
            }
        }
    }
}

// ---------------- RoPE (SIGN-FLIPPED, verified): in-place [b,heads,s,256] --
// new_x1 = x1*cos + x2*sin ; new_x2 = x2*cos - x1*sin
__global__ void rope_kernel(float* __restrict__ buf,
                            const int* __restrict__ pos_ids, int heads)
{
    const long total = (long)BATCH * heads * SEQ * 128;
    for (long idx = (long)blockIdx.x * blockDim.x + threadIdx.x; idx < total;
         idx += (long)gridDim.x * blockDim.x) {
        const int j = (int)(idx & 127);
        const int s = (int)((idx >> 7) & 2047);
        const long hh = idx >> 18;               // b*heads + head
        const long base = hh * ((long)SEQ * HDIM) + (long)s * HDIM;
        const int b = (int)(hh / heads);
        const float pos = (float)pos_ids[b * SEQ + s];
        const float invf = powf(10000.0f, -(float)j * (1.0f / 128.0f));
        const float ang = pos * invf;
        float c, sn;
        sincosf(ang, &c, &sn);
        const float x1 = buf[base + j];
        const float x2 = buf[base + j + 128];
        buf[base + j]       = x1 * c + x2 * sn;   // sign-flipped convention
        buf[base + j + 128] = x2 * c - x1 * sn;
    }
}

// ---------------- flash attention, fp32, causal, SMEM softmax --------------
#define BQ 64
#define BKK 64
#define DPAD (HDIM + 4)
#define PSTR 68

__global__ __launch_bounds__(256) void flash_kernel(
    const float* __restrict__ Q, const float* __restrict__ K,
    const float* __restrict__ V, float* __restrict__ Out)
{
    extern __shared__ float sm[];
    float* Qs   = sm;                 // [64][260]
    float* Ks   = sm + 16640;         // [64][260]
    float* Vs   = sm + 33280;         // [64][260]
    float* Ps   = sm + 49920;         // [64][68]
    float* sRed = sm + 54272;         // [64][17]
    float* sM   = sm + 55360;         // [64]
    float* sL   = sm + 55424;         // [64]
    float* sC   = sm + 55488;         // [64]   total 55552 floats = 222208 B

    const int qb = blockIdx.x;
    const int h  = blockIdx.y;
    const int b  = blockIdx.z;
    const int kvh = h >> 2;           // repeat_kv quirk: head h uses kv h/4

    const int tid = threadIdx.x;
    const int tx = tid & 15;
    const int ty = tid >> 4;

    const float* Qg = Q + (((size_t)(b*NHEADS + h))*SEQ + qb*BQ) * HDIM;
    const float* Kg = K + ((size_t)(b*NKV + kvh))*SEQ * HDIM;
    const float* Vg = V + ((size_t)(b*NKV + kvh))*SEQ * HDIM;

    for (int i = tid; i < BQ * (HDIM/4); i += 256) {
        const int r = i >> 6;
        const int c = (i & 63) * 4;
        *(float4*)&Qs[r*DPAD + c] = *(const float4*)&Qg[r*HDIM + c];
    }
    if (tid < BQ) { sM[tid] = -3.0e38f; sL[tid] = 0.f; }

    float4 O4[4][4];
#pragma unroll
    for (int i = 0; i < 4; i++)
#pragma unroll
        for (int jj = 0; jj < 4; jj++) O4[i][jj] = make_float4(0.f,0.f,0.f,0.f);

    const int nkb = qb + 1;
    for (int kb = 0; kb < nkb; kb++) {
        __syncthreads();  // prev PV done, sM/sL init done
        for (int i = tid; i < BKK * (HDIM/4); i += 256) {
            const int r = i >> 6;
            const int c = (i & 63) * 4;
            *(float4*)&Ks[r*DPAD + c] = *(const float4*)&Kg[((size_t)(kb*BKK + r))*HDIM + c];
            *(float4*)&Vs[r*DPAD + c] = *(const float4*)&Vg[((size_t)(kb*BKK + r))*HDIM + c];
        }
        __syncthreads();  // tiles ready

        // ---- scores S = Q K^T / 16 (+causal mask on diagonal tile) ----
        float s[4][4];
#pragma unroll
        for (int i = 0; i < 4; i++)
#pragma unroll
            for (int j = 0; j < 4; j++) s[i][j] = 0.f;

#pragma unroll 8
        for (int d = 0; d < HDIM; d += 4) {
            float4 q4[4], k4[4];
#pragma unroll
            for (int i = 0; i < 4; i++) q4[i] = *(const float4*)&Qs[(ty*4 + i)*DPAD + d];
#pragma unroll
            for (int j = 0; j < 4; j++) k4[j] = *(const float4*)&Ks[(tx + 16*j)*DPAD + d];
#pragma unroll
            for (int i = 0; i < 4; i++)
#pragma unroll
                for (int j = 0; j < 4; j++)
                    s[i][j] += q4[i].x*k4[j].x + q4[i].y*k4[j].y
                             + q4[i].z*k4[j].z + q4[i].w*k4[j].w;
        }

        const bool diag = (kb == qb);
#pragma unroll
        for (int i = 0; i < 4; i++) {
            const int qidx = qb*BQ + ty*4 + i;
#pragma unroll
            for (int j = 0; j < 4; j++) {
                const int kidx = kb*BKK + tx + 16*j;
                float v = s[i][j] * 0.0625f;
                if (diag && kidx > qidx) v += -1e9f;
                s[i][j] = v;
            }
        }

        // ---- phase 1: per-thread row-partial max -> sRed ----
#pragma unroll
        for (int i = 0; i < 4; i++) {
            float pm = fmaxf(fmaxf(s[i][0], s[i][1]), fmaxf(s[i][2], s[i][3]));
            sRed[(ty*4 + i)*17 + tx] = pm;
        }
        __syncthreads();

        // ---- phase 2: row owners compute new max + correction ----
        if (tid < BQ) {
            const int r = tid;
            float rm = sRed[r*17 + 0];
#pragma unroll
            for (int t = 1; t < 16; t++) rm = fmaxf(rm, sRed[r*17 + t]);
            const float mold = sM[r];
            const float mnew = fmaxf(mold, rm);
            sC[r] = expf(mold - mnew);
            sM[r] = mnew;
        }
        __syncthreads();

        // ---- phase 3: exp, write P, partial sums, rescale O ----
#pragma unroll
        for (int i = 0; i < 4; i++) {
            const int r = ty*4 + i;
            const float mnew = sM[r];
            const float corr = sC[r];
            float ps = 0.f;
#pragma unroll
            for (int j = 0; j < 4; j++) {
                const float p = expf(s[i][j] - mnew);
                Ps[r*PSTR + tx + 16*j] = p;
                ps += p;
            }
            sRed[r*17 + tx] = ps;
#pragma unroll
            for (int jj = 0; jj < 4; jj++) {
                O4[i][jj].x *= corr; O4[i][jj].y *= corr;
                O4[i][jj].z *= corr; O4[i][jj].w *= corr;
            }
        }
        __syncthreads();

        // ---- phase 4: row owners update l ----
        if (tid < BQ) {
            const int r = tid;
            float rs = 0.f;
#pragma unroll
            for (int t = 0; t < 16; t++) rs += sRed[r*17 + t];
            sL[r] = sL[r] * sC[r] + rs;
        }

        // ---- O += P V ----
#pragma unroll 4
        for (int kk = 0; kk < BKK; kk += 4) {
            float4 p4[4];
#pragma unroll
            for (int i = 0; i < 4; i++)
                p4[i] = *(const float4*)&Ps[(ty*4 + i)*PSTR + kk];
#pragma unroll
            for (int t = 0; t < 4; t++) {
                float4 v4[4];
#pragma unroll
                for (int jj = 0; jj < 4; jj++)
                    v4[jj] = *(const float4*)&Vs[(kk + t)*DPAD + jj*64 + tx*4];
#pragma unroll
                for (int i = 0; i < 4; i++) {
                    const float p = (t == 0) ? p4[i].x : (t == 1) ? p4[i].y
                                  : (t == 2) ? p4[i].z : p4[i].w;
#pragma unroll
                    for (int jj = 0; jj < 4; jj++) {
                        O4[i][jj].x += p * v4[jj].x;
                        O4[i][jj].y += p * v4[jj].y;
                        O4[i][jj].z += p * v4[jj].z;
                        O4[i][jj].w += p * v4[jj].w;
                    }
                }
            }
        }
    }
    __syncthreads();  // final sL visible

    // ---- epilogue: O /= l, write [b,s,h*256+d] ----
#pragma unroll
    for (int i = 0; i < 4; i++) {
        const int r = ty*4 + i;
        const float inv = 1.0f / sL[r];
        const int row = qb*BQ + r;
        float* outp = Out + ((size_t)(b*SEQ + row))*QKDIM + h*HDIM;
#pragma unroll
        for (int jj = 0; jj < 4; jj++) {
            float4 o = O4[i][jj];
            o.x *= inv; o.y *= inv; o.z *= inv; o.w *= inv;
            *(float4*)&outp[jj*64 + tx*4] = o;
        }
    }
}

// ---------------- launch ---------------------------------------------------
extern "C" void kernel_launch(void* const* d_in, const int* in_sizes, int n_in,
                              void* d_out, int out_size)
{
    const float* hidden = (const float*)d_in[0];
    // d_in[1] = attention_mask (causal; applied analytically — verified)
    const int*   pos    = (const int*)d_in[2];
    const float* Wq     = (const float*)d_in[3];
    const float* Wk     = (const float*)d_in[4];
    const float* Wv     = (const float*)d_in[5];
    const float* Wo     = (const float*)d_in[6];
    float* out = (float*)d_out;

    float *qb, *kb, *vb, *ab;
    cudaGetSymbolAddress((void**)&qb, g_q);
    cudaGetSymbolAddress((void**)&kb, g_k);
    cudaGetSymbolAddress((void**)&vb, g_v);
    cudaGetSymbolAddress((void**)&ab, g_attn);

    const int M = BATCH * SEQ;   // 4096

    // QKV projections (tiled SGEMM)
    {
        dim3 gq(QKDIM / BN, M / BM);  // (32,32)
        sgemm_kernel<<<gq, 256>>>(hidden, Wq, qb, M, QKDIM, HID, 1);
        dim3 gk(KVDIM / BN, M / BM);  // (8,32)
        sgemm_kernel<<<gk, 256>>>(hidden, Wk, kb, M, KVDIM, HID, 2);
        sgemm_kernel<<<gk, 256>>>(hidden, Wv, vb, M, KVDIM, HID, 2);
    }

    // RoPE on Q and K (sign-flipped, verified)
    rope_kernel<<<2048, 256>>>(qb, pos, NHEADS);
    rope_kernel<<<2048, 256>>>(kb, pos, NKV);

    // flash attention
    {
        const int smem = 55552 * (int)sizeof(float); // 222208 bytes
        cudaFuncSetAttribute(flash_kernel,
                             cudaFuncAttributeMaxDynamicSharedMemorySize, smem);
        dim3 g(SEQ / BQ, NHEADS, BATCH);  // (32,16,2)
        flash_kernel<<<g, 256, smem>>>(qb, kb, vb, ab);
    }

    // output projection -> d_out
    {
        dim3 go(HID / BN, M / BM);  // (16,32)
        sgemm_kernel<<<go, 256>>>(ab, Wo, out, M, HID, QKDIM, 0);
    }
}

// round 13
// speedup vs baseline: 8.2727x; 1.5655x over previous
#include <cuda_runtime.h>
#include <cuda_bf16.h>
#include <math.h>
#include <float.h>
#include <stdint.h>

// Problem constants
#define BATCH   2
#define SEQ     2048
#define HID     2048
#define NHEADS  16
#define NKV     4
#define HDIM    256
#define QKDIM   (NHEADS*HDIM)   // 4096
#define KVDIM   (NKV*HDIM)      // 1024

// ---------------- scratch (device globals) ---------------------------------
__device__ float g_q[BATCH*NHEADS*SEQ*HDIM];   // [b,h,s,d]
__device__ float g_k[BATCH*NKV*SEQ*HDIM];      // [b,kv,s,d]
__device__ float g_v[BATCH*NKV*SEQ*HDIM];
__device__ float g_attn[BATCH*SEQ*QKDIM];      // [b,s,h*d]

// ---------------- tf32 helpers ---------------------------------------------
__device__ __forceinline__ float f2tf32(float x)
{
    uint32_t r;
    asm("cvt.rna.tf32.f32 %0, %1;" : "=r"(r) : "f"(x));
    return __uint_as_float(r);
}

__device__ __forceinline__ void mma_tf32(float* c, const uint32_t* a, const uint32_t* b)
{
    asm volatile(
        "mma.sync.aligned.m16n8k8.row.col.f32.tf32.tf32.f32 "
        "{%0,%1,%2,%3}, {%4,%5,%6,%7}, {%8,%9}, {%0,%1,%2,%3};"
        : "+f"(c[0]), "+f"(c[1]), "+f"(c[2]), "+f"(c[3])
        : "r"(a[0]), "r"(a[1]), "r"(a[2]), "r"(a[3]), "r"(b[0]), "r"(b[1]));
}

// ---------------- tf32 tensor-core GEMM: C = A(MxK) @ B(KxN) ---------------
// Block 128x128, BK=16, 256 threads = 8 warps (4 m x 2 n), warp tile 32x64.
// mode 0: plain  mode 1: Q scatter  mode 2: KV scatter
#define ASTR 20     // As row stride (floats): conflict-free for frag loads
#define BSTR 136    // Bs row stride

__global__ __launch_bounds__(256) void tgemm_kernel(
    const float* __restrict__ A, const float* __restrict__ B,
    float* __restrict__ C, int M, int N, int K, int mode)
{
    __shared__ float As[128 * ASTR];   // [m][k] tf32 bits
    __shared__ float Bs[16 * BSTR];    // [k][n] tf32 bits

    const int tid = threadIdx.x;
    const int bm = blockIdx.y * 128;
    const int bn = blockIdx.x * 128;

    const int wid  = tid >> 5;
    const int lane = tid & 31;
    const int g = lane >> 2;          // 0..7
    const int t = lane & 3;           // 0..3
    const int wm = (wid & 3) * 32;    // warp m offset
    const int wn = (wid >> 2) * 64;   // warp n offset

    float acc[2][8][4];
#pragma unroll
    for (int i = 0; i < 2; i++)
#pragma unroll
        for (int j = 0; j < 8; j++)
#pragma unroll
            for (int c = 0; c < 4; c++) acc[i][j][c] = 0.f;

    // global->smem copy indices (512 float4 each, 2 per thread)
    const int af_row0 = tid >> 2,          af_col0 = (tid & 3) * 4;
    const int af_row1 = (tid + 256) >> 2,  af_col1 = af_col0;
    const int bf_row0 = tid >> 5,          bf_col0 = (tid & 31) * 4;
    const int bf_row1 = (tid + 256) >> 5,  bf_col1 = bf_col0;

    for (int k0 = 0; k0 < K; k0 += 16) {
        // load + convert A tile (128 x 16)
        {
            float4 v = *(const float4*)&A[(size_t)(bm + af_row0) * K + k0 + af_col0];
            float* p = &As[af_row0 * ASTR + af_col0];
            p[0] = f2tf32(v.x); p[1] = f2tf32(v.y); p[2] = f2tf32(v.z); p[3] = f2tf32(v.w);
            v = *(const float4*)&A[(size_t)(bm + af_row1) * K + k0 + af_col1];
            p = &As[af_row1 * ASTR + af_col1];
            p[0] = f2tf32(v.x); p[1] = f2tf32(v.y); p[2] = f2tf32(v.z); p[3] = f2tf32(v.w);
        }
        // load + convert B tile (16 x 128)
        {
            float4 v = *(const float4*)&B[(size_t)(k0 + bf_row0) * N + bn + bf_col0];
            float* p = &Bs[bf_row0 * BSTR + bf_col0];
            p[0] = f2tf32(v.x); p[1] = f2tf32(v.y); p[2] = f2tf32(v.z); p[3] = f2tf32(v.w);
            v = *(const float4*)&B[(size_t)(k0 + bf_row1) * N + bn + bf_col1];
            p = &Bs[bf_row1 * BSTR + bf_col1];
            p[0] = f2tf32(v.x); p[1] = f2tf32(v.y); p[2] = f2tf32(v.z); p[3] = f2tf32(v.w);
        }
        __syncthreads();

#pragma unroll
        for (int kk = 0; kk < 16; kk += 8) {
            uint32_t afr[2][4];
#pragma unroll
            for (int mt = 0; mt < 2; mt++) {
                const int m0 = wm + mt * 16;
                afr[mt][0] = __float_as_uint(As[(m0 + g) * ASTR + kk + t]);
                afr[mt][1] = __float_as_uint(As[(m0 + g + 8) * ASTR + kk + t]);
                afr[mt][2] = __float_as_uint(As[(m0 + g) * ASTR + kk + t + 4]);
                afr[mt][3] = __float_as_uint(As[(m0 + g + 8) * ASTR + kk + t + 4]);
            }
            uint32_t bfr[8][2];
#pragma unroll
            for (int nt = 0; nt < 8; nt++) {
                const int n0 = wn + nt * 8;
                bfr[nt][0] = __float_as_uint(Bs[(kk + t) * BSTR + n0 + g]);
                bfr[nt][1] = __float_as_uint(Bs[(kk + t + 4) * BSTR + n0 + g]);
            }
#pragma unroll
            for (int mt = 0; mt < 2; mt++)
#pragma unroll
                for (int nt = 0; nt < 8; nt++)
                    mma_tf32(acc[mt][nt], afr[mt], bfr[nt]);
        }
        __syncthreads();
    }

    // epilogue: c0,c1 at (row g, cols 2t,2t+1); c2,c3 at row g+8
#pragma unroll
    for (int mt = 0; mt < 2; mt++) {
#pragma unroll
        for (int nt = 0; nt < 8; nt++) {
#pragma unroll
            for (int half = 0; half < 2; half++) {
                const int m = bm + wm + mt * 16 + g + half * 8;
                const int n = bn + wn + nt * 8 + 2 * t;
                const float v0 = acc[mt][nt][half * 2 + 0];
                const float v1 = acc[mt][nt][half * 2 + 1];
                if (mode == 0) {
                    C[(size_t)m * N + n]     = v0;
                    C[(size_t)m * N + n + 1] = v1;
                } else if (mode == 1) {
                    const int bb = m >> 11, s = m & 2047;
                    const int h = n >> 8,  d = n & 255;
                    float* p = &C[(((size_t)(bb*NHEADS + h))*SEQ + s)*HDIM + d];
                    p[0] = v0; p[1] = v1;   // d,d+1 same head (n even, 2t<256)
                } else {
                    const int bb = m >> 11, s = m & 2047;
                    const int h = n >> 8,  d = n & 255;
                    float* p = &C[(((size_t)(bb*NKV + h))*SEQ + s)*HDIM + d];
                    p[0] = v0; p[1] = v1;
                }
            }
        }
    }
}

// ---------------- RoPE (SIGN-FLIPPED, verified): in-place [b,heads,s,256] --
__global__ void rope_kernel(float* __restrict__ buf,
                            const int* __restrict__ pos_ids, int heads)
{
    const long total = (long)BATCH * heads * SEQ * 128;
    for (long idx = (long)blockIdx.x * blockDim.x + threadIdx.x; idx < total;
         idx += (long)gridDim.x * blockDim.x) {
        const int j = (int)(idx & 127);
        const int s = (int)((idx >> 7) & 2047);
        const long hh = idx >> 18;
        const long base = hh * ((long)SEQ * HDIM) + (long)s * HDIM;
        const int b = (int)(hh / heads);
        const float pos = (float)pos_ids[b * SEQ + s];
        const float invf = powf(10000.0f, -(float)j * (1.0f / 128.0f));
        float c, sn;
        sincosf(pos * invf, &c, &sn);
        const float x1 = buf[base + j];
        const float x2 = buf[base + j + 128];
        buf[base + j]       = x1 * c + x2 * sn;   // sign-flipped (verified)
        buf[base + j + 128] = x2 * c - x1 * sn;
    }
}

// ---------------- flash attention, fp32, causal, SMEM softmax --------------
#define BQ 64
#define BKK 64
#define DPAD (HDIM + 4)
#define PSTR 68

__global__ __launch_bounds__(256) void flash_kernel(
    const float* __restrict__ Q, const float* __restrict__ K,
    const float* __restrict__ V, float* __restrict__ Out)
{
    extern __shared__ float sm[];
    float* Qs   = sm;                 // [64][260]
    float* Ks   = sm + 16640;
    float* Vs   = sm + 33280;
    float* Ps   = sm + 49920;         // [64][68]
    float* sRed = sm + 54272;         // [64][17]
    float* sM   = sm + 55360;
    float* sL   = sm + 55424;
    float* sC   = sm + 55488;         // total 55552 floats

    const int qb = blockIdx.x;
    const int h  = blockIdx.y;
    const int b  = blockIdx.z;
    const int kvh = h >> 2;

    const int tid = threadIdx.x;
    const int tx = tid & 15;
    const int ty = tid >> 4;

    const float* Qg = Q + (((size_t)(b*NHEADS + h))*SEQ + qb*BQ) * HDIM;
    const float* Kg = K + ((size_t)(b*NKV + kvh))*SEQ * HDIM;
    const float* Vg = V + ((size_t)(b*NKV + kvh))*SEQ * HDIM;

    for (int i = tid; i < BQ * (HDIM/4); i += 256) {
        const int r = i >> 6;
        const int c = (i & 63) * 4;
        *(float4*)&Qs[r*DPAD + c] = *(const float4*)&Qg[r*HDIM + c];
    }
    if (tid < BQ) { sM[tid] = -3.0e38f; sL[tid] = 0.f; }

    float4 O4[4][4];
#pragma unroll
    for (int i = 0; i < 4; i++)
#pragma unroll
        for (int jj = 0; jj < 4; jj++) O4[i][jj] = make_float4(0.f,0.f,0.f,0.f);

    const int nkb = qb + 1;
    for (int kb = 0; kb < nkb; kb++) {
        __syncthreads();
        for (int i = tid; i < BKK * (HDIM/4); i += 256) {
            const int r = i >> 6;
            const int c = (i & 63) * 4;
            *(float4*)&Ks[r*DPAD + c] = *(const float4*)&Kg[((size_t)(kb*BKK + r))*HDIM + c];
            *(float4*)&Vs[r*DPAD + c] = *(const float4*)&Vg[((size_t)(kb*BKK + r))*HDIM + c];
        }
        __syncthreads();

        float s[4][4];
#pragma unroll
        for (int i = 0; i < 4; i++)
#pragma unroll
            for (int j = 0; j < 4; j++) s[i][j] = 0.f;

#pragma unroll 8
        for (int d = 0; d < HDIM; d += 4) {
            float4 q4[4], k4[4];
#pragma unroll
            for (int i = 0; i < 4; i++) q4[i] = *(const float4*)&Qs[(ty*4 + i)*DPAD + d];
#pragma unroll
            for (int j = 0; j < 4; j++) k4[j] = *(const float4*)&Ks[(tx + 16*j)*DPAD + d];
#pragma unroll
            for (int i = 0; i < 4; i++)
#pragma unroll
                for (int j = 0; j < 4; j++)
                    s[i][j] += q4[i].x*k4[j].x + q4[i].y*k4[j].y
                             + q4[i].z*k4[j].z + q4[i].w*k4[j].w;
        }

        const bool diag = (kb == qb);
#pragma unroll
        for (int i = 0; i < 4; i++) {
            const int qidx = qb*BQ + ty*4 + i;
#pragma unroll
            for (int j = 0; j < 4; j++) {
                const int kidx = kb*BKK + tx + 16*j;
                float v = s[i][j] * 0.0625f;
                if (diag && kidx > qidx) v += -1e9f;
                s[i][j] = v;
            }
        }

#pragma unroll
        for (int i = 0; i < 4; i++) {
            float pm = fmaxf(fmaxf(s[i][0], s[i][1]), fmaxf(s[i][2], s[i][3]));
            sRed[(ty*4 + i)*17 + tx] = pm;
        }
        __syncthreads();

        if (tid < BQ) {
            const int r = tid;
            float rm = sRed[r*17 + 0];
#pragma unroll
            for (int tt = 1; tt < 16; tt++) rm = fmaxf(rm, sRed[r*17 + tt]);
            const float mold = sM[r];
            const float mnew = fmaxf(mold, rm);
            sC[r] = expf(mold - mnew);
            sM[r] = mnew;
        }
        __syncthreads();

#pragma unroll
        for (int i = 0; i < 4; i++) {
            const int r = ty*4 + i;
            const float mnew = sM[r];
            const float corr = sC[r];
            float ps = 0.f;
#pragma unroll
            for (int j = 0; j < 4; j++) {
                const float p = expf(s[i][j] - mnew);
                Ps[r*PSTR + tx + 16*j] = p;
                ps += p;
            }
            sRed[r*17 + tx] = ps;
#pragma unroll
            for (int jj = 0; jj < 4; jj++) {
                O4[i][jj].x *= corr; O4[i][jj].y *= corr;
                O4[i][jj].z *= corr; O4[i][jj].w *= corr;
            }
        }
        __syncthreads();

        if (tid < BQ) {
            const int r = tid;
            float rs = 0.f;
#pragma unroll
            for (int tt = 0; tt < 16; tt++) rs += sRed[r*17 + tt];
            sL[r] = sL[r] * sC[r] + rs;
        }

#pragma unroll 4
        for (int kk = 0; kk < BKK; kk += 4) {
            float4 p4[4];
#pragma unroll
            for (int i = 0; i < 4; i++)
                p4[i] = *(const float4*)&Ps[(ty*4 + i)*PSTR + kk];
#pragma unroll
            for (int tt = 0; tt < 4; tt++) {
                float4 v4[4];
#pragma unroll
                for (int jj = 0; jj < 4; jj++)
                    v4[jj] = *(const float4*)&Vs[(kk + tt)*DPAD + jj*64 + tx*4];
#pragma unroll
                for (int i = 0; i < 4; i++) {
                    const float p = (tt == 0) ? p4[i].x : (tt == 1) ? p4[i].y
                                  : (tt == 2) ? p4[i].z : p4[i].w;
#pragma unroll
                    for (int jj = 0; jj < 4; jj++) {
                        O4[i][jj].x += p * v4[jj].x;
                        O4[i][jj].y += p * v4[jj].y;
                        O4[i][jj].z += p * v4[jj].z;
                        O4[i][jj].w += p * v4[jj].w;
                    }
                }
            }
        }
    }
    __syncthreads();

#pragma unroll
    for (int i = 0; i < 4; i++) {
        const int r = ty*4 + i;
        const float inv = 1.0f / sL[r];
        const int row = qb*BQ + r;
        float* outp = Out + ((size_t)(b*SEQ + row))*QKDIM + h*HDIM;
#pragma unroll
        for (int jj = 0; jj < 4; jj++) {
            float4 o = O4[i][jj];
            o.x *= inv; o.y *= inv; o.z *= inv; o.w *= inv;
            *(float4*)&outp[jj*64 + tx*4] = o;
        }
    }
}

// ---------------- launch ---------------------------------------------------
extern "C" void kernel_launch(void* const* d_in, const int* in_sizes, int n_in,
                              void* d_out, int out_size)
{
    const float* hidden = (const float*)d_in[0];
    const int*   pos    = (const int*)d_in[2];
    const float* Wq     = (const float*)d_in[3];
    const float* Wk     = (const float*)d_in[4];
    const float* Wv     = (const float*)d_in[5];
    const float* Wo     = (const float*)d_in[6];
    float* out = (float*)d_out;

    float *qb, *kb, *vb, *ab;
    cudaGetSymbolAddress((void**)&qb, g_q);
    cudaGetSymbolAddress((void**)&kb, g_k);
    cudaGetSymbolAddress((void**)&vb, g_v);
    cudaGetSymbolAddress((void**)&ab, g_attn);

    const int M = BATCH * SEQ;   // 4096

    // QKV projections (tf32 tensor-core GEMM)
    tgemm_kernel<<<dim3(QKDIM/128, M/128), 256>>>(hidden, Wq, qb, M, QKDIM, HID, 1);
    tgemm_kernel<<<dim3(KVDIM/128, M/128), 256>>>(hidden, Wk, kb, M, KVDIM, HID, 2);
    tgemm_kernel<<<dim3(KVDIM/128, M/128), 256>>>(hidden, Wv, vb, M, KVDIM, HID, 2);

    // RoPE on Q and K (sign-flipped, verified)
    rope_kernel<<<2048, 256>>>(qb, pos, NHEADS);
    rope_kernel<<<2048, 256>>>(kb, pos, NKV);

    // flash attention (fp32, verified)
    {
        const int smem = 55552 * (int)sizeof(float);
        cudaFuncSetAttribute(flash_kernel,
                             cudaFuncAttributeMaxDynamicSharedMemorySize, smem);
        dim3 g(SEQ / BQ, NHEADS, BATCH);
        flash_kernel<<<g, 256, smem>>>(qb, kb, vb, ab);
    }

    // output projection -> d_out (tf32 tensor-core GEMM)
    tgemm_kernel<<<dim3(HID/128, M/128), 256>>>(ab, Wo, out, M, HID, QKDIM, 0);
}

// round 14
// speedup vs baseline: 11.7467x; 1.4199x over previous
#include <cuda_runtime.h>
#include <cuda_bf16.h>
#include <math.h>
#include <float.h>
#include <stdint.h>

// Problem constants
#define BATCH   2
#define SEQ     2048
#define HID     2048
#define NHEADS  16
#define NKV     4
#define HDIM    256
#define QKDIM   (NHEADS*HDIM)   // 4096
#define KVDIM   (NKV*HDIM)      // 1024

// ---------------- scratch (device globals) ---------------------------------
__device__ float g_q[BATCH*NHEADS*SEQ*HDIM];   // [b,h,s,d]
__device__ float g_k[BATCH*NKV*SEQ*HDIM];      // [b,kv,s,d]
__device__ float g_v[BATCH*NKV*SEQ*HDIM];
__device__ float g_attn[BATCH*SEQ*QKDIM];      // [b,s,h*d]

// ---------------- tf32 helpers ---------------------------------------------
__device__ __forceinline__ float f2tf32(float x)
{
    uint32_t r;
    asm("cvt.rna.tf32.f32 %0, %1;" : "=r"(r) : "f"(x));
    return __uint_as_float(r);
}

__device__ __forceinline__ void mma_tf32(float* c, const uint32_t* a, const uint32_t* b)
{
    asm volatile(
        "mma.sync.aligned.m16n8k8.row.col.f32.tf32.tf32.f32 "
        "{%0,%1,%2,%3}, {%4,%5,%6,%7}, {%8,%9}, {%0,%1,%2,%3};"
        : "+f"(c[0]), "+f"(c[1]), "+f"(c[2]), "+f"(c[3])
        : "r"(a[0]), "r"(a[1]), "r"(a[2]), "r"(a[3]), "r"(b[0]), "r"(b[1]));
}

// ---------------- tf32 tensor-core GEMM (unchanged from R13, verified) -----
#define ASTR 20
#define BSTR 136

__global__ __launch_bounds__(256) void tgemm_kernel(
    const float* __restrict__ A, const float* __restrict__ B,
    float* __restrict__ C, int M, int N, int K, int mode)
{
    __shared__ float As[128 * ASTR];
    __shared__ float Bs[16 * BSTR];

    const int tid = threadIdx.x;
    const int bm = blockIdx.y * 128;
    const int bn = blockIdx.x * 128;

    const int wid  = tid >> 5;
    const int lane = tid & 31;
    const int g = lane >> 2;
    const int t = lane & 3;
    const int wm = (wid & 3) * 32;
    const int wn = (wid >> 2) * 64;

    float acc[2][8][4];
#pragma unroll
    for (int i = 0; i < 2; i++)
#pragma unroll
        for (int j = 0; j < 8; j++)
#pragma unroll
            for (int c = 0; c < 4; c++) acc[i][j][c] = 0.f;

    const int af_row0 = tid >> 2,          af_col0 = (tid & 3) * 4;
    const int af_row1 = (tid + 256) >> 2,  af_col1 = af_col0;
    const int bf_row0 = tid >> 5,          bf_col0 = (tid & 31) * 4;
    const int bf_row1 = (tid + 256) >> 5,  bf_col1 = bf_col0;

    for (int k0 = 0; k0 < K; k0 += 16) {
        {
            float4 v = *(const float4*)&A[(size_t)(bm + af_row0) * K + k0 + af_col0];
            float* p = &As[af_row0 * ASTR + af_col0];
            p[0] = f2tf32(v.x); p[1] = f2tf32(v.y); p[2] = f2tf32(v.z); p[3] = f2tf32(v.w);
            v = *(const float4*)&A[(size_t)(bm + af_row1) * K + k0 + af_col1];
            p = &As[af_row1 * ASTR + af_col1];
            p[0] = f2tf32(v.x); p[1] = f2tf32(v.y); p[2] = f2tf32(v.z); p[3] = f2tf32(v.w);
        }
        {
            float4 v = *(const float4*)&B[(size_t)(k0 + bf_row0) * N + bn + bf_col0];
            float* p = &Bs[bf_row0 * BSTR + bf_col0];
            p[0] = f2tf32(v.x); p[1] = f2tf32(v.y); p[2] = f2tf32(v.z); p[3] = f2tf32(v.w);
            v = *(const float4*)&B[(size_t)(k0 + bf_row1) * N + bn + bf_col1];
            p = &Bs[bf_row1 * BSTR + bf_col1];
            p[0] = f2tf32(v.x); p[1] = f2tf32(v.y); p[2] = f2tf32(v.z); p[3] = f2tf32(v.w);
        }
        __syncthreads();

#pragma unroll
        for (int kk = 0; kk < 16; kk += 8) {
            uint32_t afr[2][4];
#pragma unroll
            for (int mt = 0; mt < 2; mt++) {
                const int m0 = wm + mt * 16;
                afr[mt][0] = __float_as_uint(As[(m0 + g) * ASTR + kk + t]);
                afr[mt][1] = __float_as_uint(As[(m0 + g + 8) * ASTR + kk + t]);
                afr[mt][2] = __float_as_uint(As[(m0 + g) * ASTR + kk + t + 4]);
                afr[mt][3] = __float_as_uint(As[(m0 + g + 8) * ASTR + kk + t + 4]);
            }
            uint32_t bfr[8][2];
#pragma unroll
            for (int nt = 0; nt < 8; nt++) {
                const int n0 = wn + nt * 8;
                bfr[nt][0] = __float_as_uint(Bs[(kk + t) * BSTR + n0 + g]);
                bfr[nt][1] = __float_as_uint(Bs[(kk + t + 4) * BSTR + n0 + g]);
            }
#pragma unroll
            for (int mt = 0; mt < 2; mt++)
#pragma unroll
                for (int nt = 0; nt < 8; nt++)
                    mma_tf32(acc[mt][nt], afr[mt], bfr[nt]);
        }
        __syncthreads();
    }

#pragma unroll
    for (int mt = 0; mt < 2; mt++) {
#pragma unroll
        for (int nt = 0; nt < 8; nt++) {
#pragma unroll
            for (int half = 0; half < 2; half++) {
                const int m = bm + wm + mt * 16 + g + half * 8;
                const int n = bn + wn + nt * 8 + 2 * t;
                const float v0 = acc[mt][nt][half * 2 + 0];
                const float v1 = acc[mt][nt][half * 2 + 1];
                if (mode == 0) {
                    C[(size_t)m * N + n]     = v0;
                    C[(size_t)m * N + n + 1] = v1;
                } else if (mode == 1) {
                    const int bb = m >> 11, s = m & 2047;
                    const int h = n >> 8,  d = n & 255;
                    float* p = &C[(((size_t)(bb*NHEADS + h))*SEQ + s)*HDIM + d];
                    p[0] = v0; p[1] = v1;
                } else {
                    const int bb = m >> 11, s = m & 2047;
                    const int h = n >> 8,  d = n & 255;
                    float* p = &C[(((size_t)(bb*NKV + h))*SEQ + s)*HDIM + d];
                    p[0] = v0; p[1] = v1;
                }
            }
        }
    }
}

// ---------------- RoPE (SIGN-FLIPPED, verified) ----------------------------
__global__ void rope_kernel(float* __restrict__ buf,
                            const int* __restrict__ pos_ids, int heads)
{
    const long total = (long)BATCH * heads * SEQ * 128;
    for (long idx = (long)blockIdx.x * blockDim.x + threadIdx.x; idx < total;
         idx += (long)gridDim.x * blockDim.x) {
        const int j = (int)(idx & 127);
        const int s = (int)((idx >> 7) & 2047);
        const long hh = idx >> 18;
        const long base = hh * ((long)SEQ * HDIM) + (long)s * HDIM;
        const int b = (int)(hh / heads);
        const float pos = (float)pos_ids[b * SEQ + s];
        const float invf = powf(10000.0f, -(float)j * (1.0f / 128.0f));
        float c, sn;
        sincosf(pos * invf, &c, &sn);
        const float x1 = buf[base + j];
        const float x2 = buf[base + j + 128];
        buf[base + j]       = x1 * c + x2 * sn;
        buf[base + j + 128] = x2 * c - x1 * sn;
    }
}

// ---------------- tensor-core flash attention (tf32), causal ---------------
// BQ=BK=64, 256 threads = 8 warps. Warp w: S tile rows (w&3)*16, cols (w>>2)*32;
// O tile rows (w&3)*16, cols (w>>2)*128.
#define QSTR 260    // == 4 mod 32 -> conflict-free frag gather
#define KSTR 260
#define VSTR 264    // == 8 mod 32
#define PSTR2 68    // == 4 mod 32

__global__ __launch_bounds__(256) void flash_tc_kernel(
    const float* __restrict__ Q, const float* __restrict__ K,
    const float* __restrict__ V, float* __restrict__ Out)
{
    extern __shared__ float sm[];
    float* Qs   = sm;                       // 64*260
    float* Ks   = Qs + 64 * QSTR;           // 64*260
    float* Vs   = Ks + 64 * KSTR;           // 64*264
    float* Ps   = Vs + 64 * VSTR;           // 64*68
    float* sRed = Ps + 64 * PSTR2;          // 64*5
    float* sM   = sRed + 320;
    float* sL   = sM + 64;
    float* sC   = sL + 64;                  // total 55040 floats = 220160 B

    const int qb = blockIdx.x;
    const int h  = blockIdx.y;
    const int b  = blockIdx.z;
    const int kvh = h >> 2;                 // repeat_kv quirk (verified)

    const int tid  = threadIdx.x;
    const int wid  = tid >> 5;
    const int lane = tid & 31;
    const int g = lane >> 2;
    const int t = lane & 3;
    const int wm  = (wid & 3) * 16;         // S/O row offset
    const int wnS = (wid >> 2) * 32;        // S col offset
    const int wnO = (wid >> 2) * 128;       // O col offset

    const float* Qg = Q + (((size_t)(b*NHEADS + h))*SEQ + qb*64) * HDIM;
    const float* Kg = K + ((size_t)(b*NKV + kvh))*SEQ * HDIM;
    const float* Vg = V + ((size_t)(b*NKV + kvh))*SEQ * HDIM;

    // load Q tile (cvt to tf32)
    for (int i = tid; i < 64 * 64; i += 256) {
        const int r = i >> 6;
        const int c = (i & 63) * 4;
        float4 v = *(const float4*)&Qg[r * HDIM + c];
        float* p = &Qs[r * QSTR + c];
        p[0] = f2tf32(v.x); p[1] = f2tf32(v.y); p[2] = f2tf32(v.z); p[3] = f2tf32(v.w);
    }
    if (tid < 64) { sM[tid] = -3.0e38f; sL[tid] = 0.f; }

    float oacc[16][4];
#pragma unroll
    for (int nt = 0; nt < 16; nt++)
#pragma unroll
        for (int c = 0; c < 4; c++) oacc[nt][c] = 0.f;

    const int row_q = tid >> 2;             // softmax: 4 threads per row
    const int qtr   = tid & 3;

    for (int kb = 0; kb <= qb; kb++) {
        __syncthreads();   // prev PV done; Q/sM/sL init done
        // load K,V tiles (cvt)
        for (int i = tid; i < 64 * 64; i += 256) {
            const int r = i >> 6;
            const int c = (i & 63) * 4;
            float4 v = *(const float4*)&Kg[((size_t)(kb*64 + r)) * HDIM + c];
            float* p = &Ks[r * KSTR + c];
            p[0] = f2tf32(v.x); p[1] = f2tf32(v.y); p[2] = f2tf32(v.z); p[3] = f2tf32(v.w);
            v = *(const float4*)&Vg[((size_t)(kb*64 + r)) * HDIM + c];
            p = &Vs[r * VSTR + c];
            p[0] = f2tf32(v.x); p[1] = f2tf32(v.y); p[2] = f2tf32(v.z); p[3] = f2tf32(v.w);
        }
        __syncthreads();

        // ---- S = Q K^T via mma ----
        float sacc[4][4];
#pragma unroll
        for (int nt = 0; nt < 4; nt++)
#pragma unroll
            for (int c = 0; c < 4; c++) sacc[nt][c] = 0.f;

#pragma unroll 4
        for (int d = 0; d < HDIM; d += 8) {
            uint32_t af[4];
            af[0] = __float_as_uint(Qs[(wm + g) * QSTR + d + t]);
            af[1] = __float_as_uint(Qs[(wm + g + 8) * QSTR + d + t]);
            af[2] = __float_as_uint(Qs[(wm + g) * QSTR + d + t + 4]);
            af[3] = __float_as_uint(Qs[(wm + g + 8) * QSTR + d + t + 4]);
            uint32_t bf[4][2];
#pragma unroll
            for (int nt = 0; nt < 4; nt++) {
                const int n0 = wnS + nt * 8;
                bf[nt][0] = __float_as_uint(Ks[(n0 + g) * KSTR + d + t]);
                bf[nt][1] = __float_as_uint(Ks[(n0 + g) * KSTR + d + t + 4]);
            }
#pragma unroll
            for (int nt = 0; nt < 4; nt++)
                mma_tf32(sacc[nt], af, bf[nt]);
        }

        // ---- scale + causal mask, write S -> Ps ----
        const bool diag = (kb == qb);
#pragma unroll
        for (int nt = 0; nt < 4; nt++) {
#pragma unroll
            for (int half = 0; half < 2; half++) {
                const int row = wm + g + half * 8;
                const int col = wnS + nt * 8 + 2 * t;
                const int qidx = qb * 64 + row;
                const int kidx = kb * 64 + col;
                float v0 = sacc[nt][half * 2 + 0] * 0.0625f;
                float v1 = sacc[nt][half * 2 + 1] * 0.0625f;
                if (diag) {
                    if (kidx > qidx)     v0 += -1e9f;
                    if (kidx + 1 > qidx) v1 += -1e9f;
                }
                Ps[row * PSTR2 + col]     = v0;
                Ps[row * PSTR2 + col + 1] = v1;
            }
        }
        __syncthreads();

        // ---- softmax phase 1: partial row max (4 threads/row) ----
        {
            float pm = -3.0e38f;
            const int base = row_q * PSTR2 + qtr * 16;
#pragma unroll
            for (int j = 0; j < 16; j++) pm = fmaxf(pm, Ps[base + j]);
            sRed[row_q * 5 + qtr] = pm;
        }
        __syncthreads();

        // ---- phase 2: row owners -> mnew, corr ----
        if (tid < 64) {
            float rm = fmaxf(fmaxf(sRed[tid*5+0], sRed[tid*5+1]),
                             fmaxf(sRed[tid*5+2], sRed[tid*5+3]));
            const float mold = sM[tid];
            const float mnew = fmaxf(mold, rm);
            sC[tid] = expf(mold - mnew);
            sM[tid] = mnew;
        }
        __syncthreads();

        // ---- phase 3: exp (cvt to tf32), partial sums; O rescale ----
        {
            const float mnew = sM[row_q];
            const int base = row_q * PSTR2 + qtr * 16;
            float ps = 0.f;
#pragma unroll
            for (int j = 0; j < 16; j++) {
                const float p = expf(Ps[base + j] - mnew);
                Ps[base + j] = f2tf32(p);
                ps += p;
            }
            sRed[row_q * 5 + qtr] = ps;
        }
        {
            const float corr0 = sC[wm + g];
            const float corr1 = sC[wm + g + 8];
#pragma unroll
            for (int nt = 0; nt < 16; nt++) {
                oacc[nt][0] *= corr0; oacc[nt][1] *= corr0;
                oacc[nt][2] *= corr1; oacc[nt][3] *= corr1;
            }
        }
        __syncthreads();

        // ---- phase 4: row owners update l ----
        if (tid < 64) {
            const float rs = sRed[tid*5+0] + sRed[tid*5+1]
                           + sRed[tid*5+2] + sRed[tid*5+3];
            sL[tid] = sL[tid] * sC[tid] + rs;
        }

        // ---- O += P V via mma ----
#pragma unroll
        for (int kk = 0; kk < 64; kk += 8) {
            uint32_t af[4];
            af[0] = __float_as_uint(Ps[(wm + g) * PSTR2 + kk + t]);
            af[1] = __float_as_uint(Ps[(wm + g + 8) * PSTR2 + kk + t]);
            af[2] = __float_as_uint(Ps[(wm + g) * PSTR2 + kk + t + 4]);
            af[3] = __float_as_uint(Ps[(wm + g + 8) * PSTR2 + kk + t + 4]);
#pragma unroll
            for (int nt = 0; nt < 16; nt++) {
                const int n0 = wnO + nt * 8;
                uint32_t bf[2];
                bf[0] = __float_as_uint(Vs[(kk + t) * VSTR + n0 + g]);
                bf[1] = __float_as_uint(Vs[(kk + t + 4) * VSTR + n0 + g]);
                mma_tf32(oacc[nt], af, bf);
            }
        }
    }
    __syncthreads();   // final sL visible

    // ---- epilogue: O /= l, write [b,s,h*256+d] ----
    {
        const float inv0 = 1.0f / sL[wm + g];
        const float inv1 = 1.0f / sL[wm + g + 8];
        const int row0 = qb * 64 + wm + g;
        const int row1 = row0 + 8;
        float* o0 = Out + ((size_t)(b*SEQ + row0)) * QKDIM + h * HDIM;
        float* o1 = Out + ((size_t)(b*SEQ + row1)) * QKDIM + h * HDIM;
#pragma unroll
        for (int nt = 0; nt < 16; nt++) {
            const int col = wnO + nt * 8 + 2 * t;
            o0[col]     = oacc[nt][0] * inv0;
            o0[col + 1] = oacc[nt][1] * inv0;
            o1[col]     = oacc[nt][2] * inv1;
            o1[col + 1] = oacc[nt][3] * inv1;
        }
    }
}

// ---------------- launch ---------------------------------------------------
extern "C" void kernel_launch(void* const* d_in, const int* in_sizes, int n_in,
                              void* d_out, int out_size)
{
    const float* hidden = (const float*)d_in[0];
    const int*   pos    = (const int*)d_in[2];
    const float* Wq     = (const float*)d_in[3];
    const float* Wk     = (const float*)d_in[4];
    const float* Wv     = (const float*)d_in[5];
    const float* Wo     = (const float*)d_in[6];
    float* out = (float*)d_out;

    float *qb, *kb, *vb, *ab;
    cudaGetSymbolAddress((void**)&qb, g_q);
    cudaGetSymbolAddress((void**)&kb, g_k);
    cudaGetSymbolAddress((void**)&vb, g_v);
    cudaGetSymbolAddress((void**)&ab, g_attn);

    const int M = BATCH * SEQ;   // 4096

    // QKV projections (tf32 tensor-core GEMM, verified)
    tgemm_kernel<<<dim3(QKDIM/128, M/128), 256>>>(hidden, Wq, qb, M, QKDIM, HID, 1);
    tgemm_kernel<<<dim3(KVDIM/128, M/128), 256>>>(hidden, Wk, kb, M, KVDIM, HID, 2);
    tgemm_kernel<<<dim3(KVDIM/128, M/128), 256>>>(hidden, Wv, vb, M, KVDIM, HID, 2);

    // RoPE (sign-flipped, verified)
    rope_kernel<<<2048, 256>>>(qb, pos, NHEADS);
    rope_kernel<<<2048, 256>>>(kb, pos, NKV);

    // tensor-core flash attention
    {
        const int smem = 55040 * (int)sizeof(float); // 220160 B
        cudaFuncSetAttribute(flash_tc_kernel,
                             cudaFuncAttributeMaxDynamicSharedMemorySize, smem);
        dim3 g(SEQ / 64, NHEADS, BATCH);
        flash_tc_kernel<<<g, 256, smem>>>(qb, kb, vb, ab);
    }

    // output projection -> d_out
    tgemm_kernel<<<dim3(HID/128, M/128), 256>>>(ab, Wo, out, M, HID, QKDIM, 0);
}

// round 15
// speedup vs baseline: 13.5414x; 1.1528x over previous
#include <cuda_runtime.h>
#include <cuda_bf16.h>
#include <math.h>
#include <float.h>
#include <stdint.h>

// Problem constants
#define BATCH   2
#define SEQ     2048
#define HID     2048
#define NHEADS  16
#define NKV     4
#define HDIM    256
#define QKDIM   (NHEADS*HDIM)   // 4096
#define KVDIM   (NKV*HDIM)      // 1024

// ---------------- scratch (device globals) ---------------------------------
__device__ float g_q[BATCH*NHEADS*SEQ*HDIM];   // [b,h,s,d]
__device__ float g_k[BATCH*NKV*SEQ*HDIM];      // [b,kv,s,d]
__device__ float g_v[BATCH*NKV*SEQ*HDIM];
__device__ float g_attn[BATCH*SEQ*QKDIM];      // [b,s,h*d]

// ---------------- tf32 / mma / cp.async helpers ----------------------------
__device__ __forceinline__ float f2tf32(float x)
{
    uint32_t r;
    asm("cvt.rna.tf32.f32 %0, %1;" : "=r"(r) : "f"(x));
    return __uint_as_float(r);
}

__device__ __forceinline__ uint32_t f2tf32b(float x)
{
    uint32_t r;
    asm("cvt.rna.tf32.f32 %0, %1;" : "=r"(r) : "f"(x));
    return r;
}

__device__ __forceinline__ void mma_tf32(float* c, const uint32_t* a, const uint32_t* b)
{
    asm volatile(
        "mma.sync.aligned.m16n8k8.row.col.f32.tf32.tf32.f32 "
        "{%0,%1,%2,%3}, {%4,%5,%6,%7}, {%8,%9}, {%0,%1,%2,%3};"
        : "+f"(c[0]), "+f"(c[1]), "+f"(c[2]), "+f"(c[3])
        : "r"(a[0]), "r"(a[1]), "r"(a[2]), "r"(a[3]), "r"(b[0]), "r"(b[1]));
}

__device__ __forceinline__ void cp_async16(float* smem_dst, const float* gmem_src)
{
    uint32_t s = (uint32_t)__cvta_generic_to_shared(smem_dst);
    asm volatile("cp.async.cg.shared.global [%0], [%1], 16;" :: "r"(s), "l"(gmem_src));
}

// ---------------- tf32 GEMM v2: double-buffered cp.async, BK=32 ------------
// Block 128x128, 256 threads = 8 warps (4m x 2n), warp tile 32x64.
// Smem holds raw fp32; tf32 cvt at fragment gather (same numerics as R13/14).
#define BK2   32
#define ASTR2 36     // A smem row stride (36 mod 32 = 4 -> conflict-free)
#define BSTR2 136    // B smem row stride (136 mod 32 = 8)
#define A_TILE (128 * ASTR2)   // 4608 floats
#define B_TILE (32 * BSTR2)    // 4352 floats
#define TG_SMEM ((2 * A_TILE + 2 * B_TILE) * 4)   // 71680 bytes

__global__ __launch_bounds__(256) void tgemm2_kernel(
    const float* __restrict__ A, const float* __restrict__ B,
    float* __restrict__ C, int M, int N, int K, int mode)
{
    extern __shared__ float dsm[];
    float* Asm[2] = { dsm, dsm + A_TILE };
    float* Bsm[2] = { dsm + 2 * A_TILE, dsm + 2 * A_TILE + B_TILE };

    const int tid = threadIdx.x;
    const int bm = blockIdx.y * 128;
    const int bn = blockIdx.x * 128;

    const int wid  = tid >> 5;
    const int lane = tid & 31;
    const int g = lane >> 2;
    const int t = lane & 3;
    const int wm = (wid & 3) * 32;
    const int wn = (wid >> 2) * 64;

    float acc[2][8][4];
#pragma unroll
    for (int i = 0; i < 2; i++)
#pragma unroll
        for (int j = 0; j < 8; j++)
#pragma unroll
            for (int c = 0; c < 4; c++) acc[i][j][c] = 0.f;

    // A tile: 128 rows x 32 cols = 1024 float4 chunks; 4 per thread
    // B tile: 32 rows x 128 cols = 1024 float4 chunks; 4 per thread
    auto load_tiles = [&](int k0, int buf) {
#pragma unroll
        for (int i = 0; i < 4; i++) {
            const int c = tid + i * 256;
            const int ar = c >> 3, ac4 = (c & 7) * 4;
            cp_async16(&Asm[buf][ar * ASTR2 + ac4],
                       &A[(size_t)(bm + ar) * K + k0 + ac4]);
            const int br = c >> 5, bc4 = (c & 31) * 4;
            cp_async16(&Bsm[buf][br * BSTR2 + bc4],
                       &B[(size_t)(k0 + br) * N + bn + bc4]);
        }
    };

    // prefetch slab 0
    load_tiles(0, 0);
    asm volatile("cp.async.commit_group;");

    int buf = 0;
    for (int k0 = 0; k0 < K; k0 += BK2, buf ^= 1) {
        const bool has_next = (k0 + BK2 < K);
        if (has_next) {
            load_tiles(k0 + BK2, buf ^ 1);
            asm volatile("cp.async.commit_group;");
            asm volatile("cp.async.wait_group 1;");
        } else {
            asm volatile("cp.async.wait_group 0;");
        }
        __syncthreads();

        const float* As = Asm[buf];
        const float* Bs = Bsm[buf];
#pragma unroll
        for (int kk = 0; kk < BK2; kk += 8) {
            uint32_t afr[2][4];
#pragma unroll
            for (int mt = 0; mt < 2; mt++) {
                const int m0 = wm + mt * 16;
                afr[mt][0] = f2tf32b(As[(m0 + g) * ASTR2 + kk + t]);
                afr[mt][1] = f2tf32b(As[(m0 + g + 8) * ASTR2 + kk + t]);
                afr[mt][2] = f2tf32b(As[(m0 + g) * ASTR2 + kk + t + 4]);
                afr[mt][3] = f2tf32b(As[(m0 + g + 8) * ASTR2 + kk + t + 4]);
            }
            uint32_t bfr[8][2];
#pragma unroll
            for (int nt = 0; nt < 8; nt++) {
                const int n0 = wn + nt * 8;
                bfr[nt][0] = f2tf32b(Bs[(kk + t) * BSTR2 + n0 + g]);
                bfr[nt][1] = f2tf32b(Bs[(kk + t + 4) * BSTR2 + n0 + g]);
            }
#pragma unroll
            for (int mt = 0; mt < 2; mt++)
#pragma unroll
                for (int nt = 0; nt < 8; nt++)
                    mma_tf32(acc[mt][nt], afr[mt], bfr[nt]);
        }
        __syncthreads();
    }

    // epilogue (verified mapping): c0,c1 at (g, 2t/2t+1); c2,c3 at g+8
#pragma unroll
    for (int mt = 0; mt < 2; mt++) {
#pragma unroll
        for (int nt = 0; nt < 8; nt++) {
#pragma unroll
            for (int half = 0; half < 2; half++) {
                const int m = bm + wm + mt * 16 + g + half * 8;
                const int n = bn + wn + nt * 8 + 2 * t;
                const float v0 = acc[mt][nt][half * 2 + 0];
                const float v1 = acc[mt][nt][half * 2 + 1];
                if (mode == 0) {
                    C[(size_t)m * N + n]     = v0;
                    C[(size_t)m * N + n + 1] = v1;
                } else if (mode == 1) {
                    const int bb = m >> 11, s = m & 2047;
                    const int h = n >> 8,  d = n & 255;
                    float* p = &C[(((size_t)(bb*NHEADS + h))*SEQ + s)*HDIM + d];
                    p[0] = v0; p[1] = v1;
                } else {
                    const int bb = m >> 11, s = m & 2047;
                    const int h = n >> 8,  d = n & 255;
                    float* p = &C[(((size_t)(bb*NKV + h))*SEQ + s)*HDIM + d];
                    p[0] = v0; p[1] = v1;
                }
            }
        }
    }
}

// ---------------- RoPE (SIGN-FLIPPED, verified) ----------------------------
__global__ void rope_kernel(float* __restrict__ buf,
                            const int* __restrict__ pos_ids, int heads)
{
    const long total = (long)BATCH * heads * SEQ * 128;
    for (long idx = (long)blockIdx.x * blockDim.x + threadIdx.x; idx < total;
         idx += (long)gridDim.x * blockDim.x) {
        const int j = (int)(idx & 127);
        const int s = (int)((idx >> 7) & 2047);
        const long hh = idx >> 18;
        const long base = hh * ((long)SEQ * HDIM) + (long)s * HDIM;
        const int b = (int)(hh / heads);
        const float pos = (float)pos_ids[b * SEQ + s];
        const float invf = powf(10000.0f, -(float)j * (1.0f / 128.0f));
        float c, sn;
        sincosf(pos * invf, &c, &sn);
        const float x1 = buf[base + j];
        const float x2 = buf[base + j + 128];
        buf[base + j]       = x1 * c + x2 * sn;
        buf[base + j + 128] = x2 * c - x1 * sn;
    }
}

// ---------------- tensor-core flash attention (tf32, verified R14) ---------
#define QSTR 260
#define KSTR 260
#define VSTR 264
#define PSTR2 68

__global__ __launch_bounds__(256) void flash_tc_kernel(
    const float* __restrict__ Q, const float* __restrict__ K,
    const float* __restrict__ V, float* __restrict__ Out)
{
    extern __shared__ float sm[];
    float* Qs   = sm;
    float* Ks   = Qs + 64 * QSTR;
    float* Vs   = Ks + 64 * KSTR;
    float* Ps   = Vs + 64 * VSTR;
    float* sRed = Ps + 64 * PSTR2;
    float* sM   = sRed + 320;
    float* sL   = sM + 64;
    float* sC   = sL + 64;

    const int qb = blockIdx.x;
    const int h  = blockIdx.y;
    const int b  = blockIdx.z;
    const int kvh = h >> 2;

    const int tid  = threadIdx.x;
    const int wid  = tid >> 5;
    const int lane = tid & 31;
    const int g = lane >> 2;
    const int t = lane & 3;
    const int wm  = (wid & 3) * 16;
    const int wnS = (wid >> 2) * 32;
    const int wnO = (wid >> 2) * 128;

    const float* Qg = Q + (((size_t)(b*NHEADS + h))*SEQ + qb*64) * HDIM;
    const float* Kg = K + ((size_t)(b*NKV + kvh))*SEQ * HDIM;
    const float* Vg = V + ((size_t)(b*NKV + kvh))*SEQ * HDIM;

    for (int i = tid; i < 64 * 64; i += 256) {
        const int r = i >> 6;
        const int c = (i & 63) * 4;
        float4 v = *(const float4*)&Qg[r * HDIM + c];
        float* p = &Qs[r * QSTR + c];
        p[0] = f2tf32(v.x); p[1] = f2tf32(v.y); p[2] = f2tf32(v.z); p[3] = f2tf32(v.w);
    }
    if (tid < 64) { sM[tid] = -3.0e38f; sL[tid] = 0.f; }

    float oacc[16][4];
#pragma unroll
    for (int nt = 0; nt < 16; nt++)
#pragma unroll
        for (int c = 0; c < 4; c++) oacc[nt][c] = 0.f;

    const int row_q = tid >> 2;
    const int qtr   = tid & 3;

    for (int kb = 0; kb <= qb; kb++) {
        __syncthreads();
        for (int i = tid; i < 64 * 64; i += 256) {
            const int r = i >> 6;
            const int c = (i & 63) * 4;
            float4 v = *(const float4*)&Kg[((size_t)(kb*64 + r)) * HDIM + c];
            float* p = &Ks[r * KSTR + c];
            p[0] = f2tf32(v.x); p[1] = f2tf32(v.y); p[2] = f2tf32(v.z); p[3] = f2tf32(v.w);
            v = *(const float4*)&Vg[((size_t)(kb*64 + r)) * HDIM + c];
            p = &Vs[r * VSTR + c];
            p[0] = f2tf32(v.x); p[1] = f2tf32(v.y); p[2] = f2tf32(v.z); p[3] = f2tf32(v.w);
        }
        __syncthreads();

        float sacc[4][4];
#pragma unroll
        for (int nt = 0; nt < 4; nt++)
#pragma unroll
            for (int c = 0; c < 4; c++) sacc[nt][c] = 0.f;

#pragma unroll 4
        for (int d = 0; d < HDIM; d += 8) {
            uint32_t af[4];
            af[0] = __float_as_uint(Qs[(wm + g) * QSTR + d + t]);
            af[1] = __float_as_uint(Qs[(wm + g + 8) * QSTR + d + t]);
            af[2] = __float_as_uint(Qs[(wm + g) * QSTR + d + t + 4]);
            af[3] = __float_as_uint(Qs[(wm + g + 8) * QSTR + d + t + 4]);
            uint32_t bf[4][2];
#pragma unroll
            for (int nt = 0; nt < 4; nt++) {
                const int n0 = wnS + nt * 8;
                bf[nt][0] = __float_as_uint(Ks[(n0 + g) * KSTR + d + t]);
                bf[nt][1] = __float_as_uint(Ks[(n0 + g) * KSTR + d + t + 4]);
            }
#pragma unroll
            for (int nt = 0; nt < 4; nt++)
                mma_tf32(sacc[nt], af, bf[nt]);
        }

        const bool diag = (kb == qb);
#pragma unroll
        for (int nt = 0; nt < 4; nt++) {
#pragma unroll
            for (int half = 0; half < 2; half++) {
                const int row = wm + g + half * 8;
                const int col = wnS + nt * 8 + 2 * t;
                const int qidx = qb * 64 + row;
                const int kidx = kb * 64 + col;
                float v0 = sacc[nt][half * 2 + 0] * 0.0625f;
                float v1 = sacc[nt][half * 2 + 1] * 0.0625f;
                if (diag) {
                    if (kidx > qidx)     v0 += -1e9f;
                    if (kidx + 1 > qidx) v1 += -1e9f;
                }
                Ps[row * PSTR2 + col]     = v0;
                Ps[row * PSTR2 + col + 1] = v1;
            }
        }
        __syncthreads();

        {
            float pm = -3.0e38f;
            const int base = row_q * PSTR2 + qtr * 16;
#pragma unroll
            for (int j = 0; j < 16; j++) pm = fmaxf(pm, Ps[base + j]);
            sRed[row_q * 5 + qtr] = pm;
        }
        __syncthreads();

        if (tid < 64) {
            float rm = fmaxf(fmaxf(sRed[tid*5+0], sRed[tid*5+1]),
                             fmaxf(sRed[tid*5+2], sRed[tid*5+3]));
            const float mold = sM[tid];
            const float mnew = fmaxf(mold, rm);
            sC[tid] = expf(mold - mnew);
            sM[tid] = mnew;
        }
        __syncthreads();

        {
            const float mnew = sM[row_q];
            const int base = row_q * PSTR2 + qtr * 16;
            float ps = 0.f;
#pragma unroll
            for (int j = 0; j < 16; j++) {
                const float p = expf(Ps[base + j] - mnew);
                Ps[base + j] = f2tf32(p);
                ps += p;
            }
            sRed[row_q * 5 + qtr] = ps;
        }
        {
            const float corr0 = sC[wm + g];
            const float corr1 = sC[wm + g + 8];
#pragma unroll
            for (int nt = 0; nt < 16; nt++) {
                oacc[nt][0] *= corr0; oacc[nt][1] *= corr0;
                oacc[nt][2] *= corr1; oacc[nt][3] *= corr1;
            }
        }
        __syncthreads();

        if (tid < 64) {
            const float rs = sRed[tid*5+0] + sRed[tid*5+1]
                           + sRed[tid*5+2] + sRed[tid*5+3];
            sL[tid] = sL[tid] * sC[tid] + rs;
        }

#pragma unroll
        for (int kk = 0; kk < 64; kk += 8) {
            uint32_t af[4];
            af[0] = __float_as_uint(Ps[(wm + g) * PSTR2 + kk + t]);
            af[1] = __float_as_uint(Ps[(wm + g + 8) * PSTR2 + kk + t]);
            af[2] = __float_as_uint(Ps[(wm + g) * PSTR2 + kk + t + 4]);
            af[3] = __float_as_uint(Ps[(wm + g + 8) * PSTR2 + kk + t + 4]);
#pragma unroll
            for (int nt = 0; nt < 16; nt++) {
                const int n0 = wnO + nt * 8;
                uint32_t bf[2];
                bf[0] = __float_as_uint(Vs[(kk + t) * VSTR + n0 + g]);
                bf[1] = __float_as_uint(Vs[(kk + t + 4) * VSTR + n0 + g]);
                mma_tf32(oacc[nt], af, bf);
            }
        }
    }
    __syncthreads();

    {
        const float inv0 = 1.0f / sL[wm + g];
        const float inv1 = 1.0f / sL[wm + g + 8];
        const int row0 = qb * 64 + wm + g;
        const int row1 = row0 + 8;
        float* o0 = Out + ((size_t)(b*SEQ + row0)) * QKDIM + h * HDIM;
        float* o1 = Out + ((size_t)(b*SEQ + row1)) * QKDIM + h * HDIM;
#pragma unroll
        for (int nt = 0; nt < 16; nt++) {
            const int col = wnO + nt * 8 + 2 * t;
            o0[col]     = oacc[nt][0] * inv0;
            o0[col + 1] = oacc[nt][1] * inv0;
            o1[col]     = oacc[nt][2] * inv1;
            o1[col + 1] = oacc[nt][3] * inv1;
        }
    }
}

// ---------------- launch ---------------------------------------------------
extern "C" void kernel_launch(void* const* d_in, const int* in_sizes, int n_in,
                              void* d_out, int out_size)
{
    const float* hidden = (const float*)d_in[0];
    const int*   pos    = (const int*)d_in[2];
    const float* Wq     = (const float*)d_in[3];
    const float* Wk     = (const float*)d_in[4];
    const float* Wv     = (const float*)d_in[5];
    const float* Wo     = (const float*)d_in[6];
    float* out = (float*)d_out;

    float *qb, *kb, *vb, *ab;
    cudaGetSymbolAddress((void**)&qb, g_q);
    cudaGetSymbolAddress((void**)&kb, g_k);
    cudaGetSymbolAddress((void**)&vb, g_v);
    cudaGetSymbolAddress((void**)&ab, g_attn);

    const int M = BATCH * SEQ;   // 4096

    // QKV projections (double-buffered tf32 GEMM)
    cudaFuncSetAttribute(tgemm2_kernel,
                         cudaFuncAttributeMaxDynamicSharedMemorySize, TG_SMEM);
    tgemm2_kernel<<<dim3(QKDIM/128, M/128), 256, TG_SMEM>>>(hidden, Wq, qb, M, QKDIM, HID, 1);
    tgemm2_kernel<<<dim3(KVDIM/128, M/128), 256, TG_SMEM>>>(hidden, Wk, kb, M, KVDIM, HID, 2);
    tgemm2_kernel<<<dim3(KVDIM/128, M/128), 256, TG_SMEM>>>(hidden, Wv, vb, M, KVDIM, HID, 2);

    // RoPE (sign-flipped, verified)
    rope_kernel<<<2048, 256>>>(qb, pos, NHEADS);
    rope_kernel<<<2048, 256>>>(kb, pos, NKV);

    // tensor-core flash attention (verified R14)
    {
        const int smem = 55040 * (int)sizeof(float);
        cudaFuncSetAttribute(flash_tc_kernel,
                             cudaFuncAttributeMaxDynamicSharedMemorySize, smem);
        dim3 g(SEQ / 64, NHEADS, BATCH);
        flash_tc_kernel<<<g, 256, smem>>>(qb, kb, vb, ab);
    }

    // output projection -> d_out
    tgemm2_kernel<<<dim3(HID/128, M/128), 256, TG_SMEM>>>(ab, Wo, out, M, HID, QKDIM, 0);
}